// round 3
// baseline (speedup 1.0000x reference)
#include <cuda_runtime.h>
#include <cstdint>
#include <cstring>
#include <cstdio>
#include <cstdlib>

#define WC 48
#define NCELL (48*48*48)
#define TFULL 96
#define TTRI 48
#define OS_A 117649
#define OS_X 2401
#define OS_Y 49

struct Tables {
    uint32_t tri[TTRI];   // e0 | e1<<8 | e2<<16
    int32_t  slot[TFULL]; // topology column -> slot [0,48) or -1
};

__device__ float4 g_sm[NCELL];
__device__ double g_loss;

__global__ void k_init() { g_loss = 0.0; }

__global__ __launch_bounds__(128) void k_field(
    const float* __restrict__ off, const float* __restrict__ topo, Tables tb)
{
    __shared__ float sv[128][37];
    __shared__ float st[128][49];
    const int tid = threadIdx.x;
    const int cell0 = blockIdx.x * 128;

    const float4* t4 = reinterpret_cast<const float4*>(topo) + (size_t)cell0 * 24;
    #pragma unroll
    for (int it = 0; it < 24; ++it) {
        int i = tid + it * 128;
        float4 v = t4[i];
        int r = i / 24, c0 = (i % 24) * 4, sl;
        sl = tb.slot[c0 + 0]; if (sl >= 0) st[r][sl] = v.x;
        sl = tb.slot[c0 + 1]; if (sl >= 0) st[r][sl] = v.y;
        sl = tb.slot[c0 + 2]; if (sl >= 0) st[r][sl] = v.z;
        sl = tb.slot[c0 + 3]; if (sl >= 0) st[r][sl] = v.w;
    }

    const int c = cell0 + tid;
    const int z = c % WC, y = (c / WC) % WC, x = c / (WC * WC);
    const float* ob = off + x * OS_X + y * OS_Y + z;

    float d;
    d = ob[0];                 sv[tid][0]=0.5f+d;  sv[tid][1]=0.0f;    sv[tid][2]=0.0f;
    d = ob[OS_Y];              sv[tid][3]=0.5f+d;  sv[tid][4]=1.0f;    sv[tid][5]=0.0f;
    d = ob[1];                 sv[tid][6]=0.5f+d;  sv[tid][7]=0.0f;    sv[tid][8]=1.0f;
    d = ob[OS_Y+1];            sv[tid][9]=0.5f+d;  sv[tid][10]=1.0f;   sv[tid][11]=1.0f;
    d = ob[OS_A];              sv[tid][12]=0.0f;   sv[tid][13]=0.5f+d; sv[tid][14]=0.0f;
    d = ob[OS_A+OS_X];         sv[tid][15]=1.0f;   sv[tid][16]=0.5f+d; sv[tid][17]=0.0f;
    d = ob[OS_A+1];            sv[tid][18]=0.0f;   sv[tid][19]=0.5f+d; sv[tid][20]=1.0f;
    d = ob[OS_A+OS_X+1];       sv[tid][21]=1.0f;   sv[tid][22]=0.5f+d; sv[tid][23]=1.0f;
    d = ob[2*OS_A];            sv[tid][24]=0.0f;   sv[tid][25]=0.0f;   sv[tid][26]=0.5f+d;
    d = ob[2*OS_A+OS_X];       sv[tid][27]=1.0f;   sv[tid][28]=0.0f;   sv[tid][29]=0.5f+d;
    d = ob[2*OS_A+OS_Y];       sv[tid][30]=0.0f;   sv[tid][31]=1.0f;   sv[tid][32]=0.5f+d;
    d = ob[2*OS_A+OS_X+OS_Y];  sv[tid][33]=1.0f;   sv[tid][34]=1.0f;   sv[tid][35]=0.5f+d;

    __syncthreads();

    float s_ = 0.f, mx = 0.f, my = 0.f, mz = 0.f;
    const float* vrow = sv[tid];
    const float* trow = st[tid];
    #pragma unroll 4
    for (int t = 0; t < TTRI; ++t) {
        uint32_t pk = tb.tri[t];
        int e0 = (pk & 0xffu) * 3, e1 = ((pk >> 8) & 0xffu) * 3, e2 = ((pk >> 16) & 0xffu) * 3;
        float v0x = vrow[e0], v0y = vrow[e0+1], v0z = vrow[e0+2];
        float ax = vrow[e1]-v0x, ay = vrow[e1+1]-v0y, az = vrow[e1+2]-v0z;
        float bx = vrow[e2]-v0x, by = vrow[e2+1]-v0y, bz = vrow[e2+2]-v0z;
        float nx = fmaf(ay, bz, -az*by);
        float ny = fmaf(az, bx, -ax*bz);
        float nz = fmaf(ax, by, -ay*bx);
        float inv = rsqrtf(fmaf(nx, nx, fmaf(ny, ny, fmaf(nz, nz, 1e-8f))));
        float p = trow[t];
        s_ += p;
        float w = p * inv;
        mx = fmaf(w, nx, mx); my = fmaf(w, ny, my); mz = fmaf(w, nz, mz);
    }
    g_sm[c] = make_float4(s_, mx, my, mz);
}

__global__ __launch_bounds__(256) void k_pair()
{
    int c = blockIdx.x * 256 + threadIdx.x;
    int z = c % WC, xy = c / WC, y = xy % WC, x = xy / WC;
    float4 a = g_sm[c];
    float acc = a.x*a.x - a.y*a.y - a.z*a.z - a.w*a.w;
    if (x < WC-1) { float4 b = g_sm[c + WC*WC]; acc += a.x*b.x - a.y*b.y - a.z*b.z - a.w*b.w; }
    if (y < WC-1) { float4 b = g_sm[c + WC];    acc += a.x*b.x - a.y*b.y - a.z*b.z - a.w*b.w; }
    if (z < WC-1) { float4 b = g_sm[c + 1];     acc += a.x*b.x - a.y*b.y - a.z*b.z - a.w*b.w; }
    acc *= 2.0f;
    #pragma unroll
    for (int o = 16; o > 0; o >>= 1) acc += __shfl_down_sync(0xffffffffu, acc, o);
    __shared__ float red[8];
    if ((threadIdx.x & 31) == 0) red[threadIdx.x >> 5] = acc;
    __syncthreads();
    if (threadIdx.x < 8) {
        float v = red[threadIdx.x];
        #pragma unroll
        for (int o = 4; o > 0; o >>= 1) v += __shfl_down_sync(0xffu, v, o);
        if (threadIdx.x == 0) atomicAdd(&g_loss, (double)v);
    }
}

__global__ void k_fin(float* out) { out[0] = (float)g_loss; }

// ---- ground truth tables from in-container python/numpy ----
static const char* PY_CMD =
    "python3 -c 'import numpy as np;r=np.random.default_rng(0);"
    "a=[r.choice(12,size=3,replace=False) for _ in range(48)];"
    "b=np.sort(r.choice(96,size=48,replace=False));"
    "print(\"TRI=\"+\",\".join(str(int(v)) for t in a for v in t));"
    "print(\"TT=\"+\",\".join(str(int(v)) for v in b))' 2>/dev/null";

static bool tables_from_python(Tables* tb)
{
    FILE* f = popen(PY_CMD, "r");
    if (!f) return false;
    char l1[1200], l2[1200];
    bool ok = fgets(l1, sizeof l1, f) && fgets(l2, sizeof l2, f) &&
              !strncmp(l1, "TRI=", 4) && !strncmp(l2, "TT=", 3);
    pclose(f);
    if (!ok) return false;
    const char* p = l1 + 4;
    for (int t = 0; t < TTRI; ++t) {
        long e[3];
        for (int k = 0; k < 3; ++k) {
            char* end; e[k] = strtol(p, &end, 10);
            if (end == p || e[k] < 0 || e[k] > 11) return false;
            p = end; if (*p == ',') ++p;
        }
        tb->tri[t] = (uint32_t)e[0] | ((uint32_t)e[1] << 8) | ((uint32_t)e[2] << 16);
    }
    for (int i = 0; i < TFULL; ++i) tb->slot[i] = -1;
    p = l2 + 3;
    long prev = -1;
    for (int k = 0; k < TTRI; ++k) {
        char* end; long v = strtol(p, &end, 10);
        if (end == p || v <= prev || v >= TFULL) return false;
        tb->slot[v] = k; prev = v; p = end; if (*p == ',') ++p;
    }
    return true;
}

// ---- fallback: SeedSequence(0)+PCG64, Lemire draws in Floyd AND shuffle ----
static void build_tables_fallback(Tables* tb)
{
    uint32_t hc = 0x43b0d7e5u;
    auto hashmix = [&hc](uint32_t v) { v ^= hc; hc *= 0x931e8875u; v *= hc; v ^= v >> 16; return v; };
    auto mixf = [](uint32_t a, uint32_t b) { uint32_t r = a*0xca01f9ddu - b*0x4973f715u; return r ^ (r >> 16); };
    uint32_t pool[4];
    for (int i = 0; i < 4; ++i) pool[i] = hashmix(0u);
    for (int s = 0; s < 4; ++s) for (int d2 = 0; d2 < 4; ++d2)
        if (s != d2) pool[d2] = mixf(pool[d2], hashmix(pool[s]));
    uint32_t hb = 0x8b51f9ddu, w[8];
    for (int i = 0; i < 8; ++i) {
        uint32_t v = pool[i % 4]; v ^= hb; hb *= 0x58f38dedu; v *= hb; v ^= v >> 16; w[i] = v;
    }
    uint64_t u64[4];
    for (int k = 0; k < 4; ++k) u64[k] = (uint64_t)w[2*k] | ((uint64_t)w[2*k+1] << 32);

    const __uint128_t MULT = ((__uint128_t)0x2360ed051fc65da4ULL << 64) | 0x4385df649fccf645ULL;
    __uint128_t inc = ((((__uint128_t)u64[2] << 64) | u64[3]) << 1) | 1;
    __uint128_t state = 0;
    state = state * MULT + inc;
    state += ((__uint128_t)u64[0] << 64) | u64[1];
    state = state * MULT + inc;

    bool has32 = false; uint32_t buf32 = 0;
    auto next32 = [&]() -> uint32_t {
        if (has32) { has32 = false; return buf32; }
        state = state * MULT + inc;
        uint64_t hi = (uint64_t)(state >> 64), lo = (uint64_t)state;
        unsigned rot = (unsigned)(hi >> 58);
        uint64_t v = hi ^ lo;
        uint64_t n = (v >> rot) | (v << ((64u - rot) & 63u));
        has32 = true; buf32 = (uint32_t)(n >> 32);
        return (uint32_t)n;
    };
    auto lemire = [&](uint32_t rng) -> uint32_t {   // [0, rng] inclusive
        if (rng == 0) return 0;
        uint32_t rng_excl = rng + 1u;
        uint64_t m = (uint64_t)next32() * rng_excl;
        uint32_t left = (uint32_t)m;
        if (left < rng_excl) {
            uint32_t thr = (0xFFFFFFFFu - rng) % rng_excl;
            while (left < thr) { m = (uint64_t)next32() * rng_excl; left = (uint32_t)m; }
        }
        return (uint32_t)(m >> 32);
    };
    auto choice = [&](int pop, int size, int64_t* out) {
        uint64_t ss = (uint64_t)(1.2 * (double)size), mask = ss;
        mask |= mask>>1; mask |= mask>>2; mask |= mask>>4; mask |= mask>>8; mask |= mask>>16; mask |= mask>>32;
        int set_size = (int)(mask + 1);
        uint64_t hs[128];
        for (int i = 0; i < set_size; ++i) hs[i] = ~0ULL;
        int k = 0;
        for (int j = pop - size; j < pop; ++j, ++k) {
            uint64_t val = lemire((uint32_t)j);
            uint64_t loc = val & mask;
            while (hs[loc] != ~0ULL && hs[loc] != val) loc = (loc + 1) & mask;
            if (hs[loc] == ~0ULL) { hs[loc] = val; out[k] = (int64_t)val; }
            else {
                loc = (uint64_t)j & mask;
                while (hs[loc] != ~0ULL) loc = (loc + 1) & mask;
                hs[loc] = (uint64_t)j; out[k] = j;
            }
        }
        for (int i = size - 1; i >= 1; --i) {
            uint32_t j = lemire((uint32_t)i);
            int64_t t = out[i]; out[i] = out[j]; out[j] = t;
        }
    };

    int64_t tmp[TTRI];
    for (int t = 0; t < TTRI; ++t) {
        choice(12, 3, tmp);
        tb->tri[t] = (uint32_t)tmp[0] | ((uint32_t)tmp[1] << 8) | ((uint32_t)tmp[2] << 16);
    }
    choice(TFULL, TTRI, tmp);
    for (int i = 1; i < TTRI; ++i) {
        int64_t key = tmp[i]; int j = i - 1;
        while (j >= 0 && tmp[j] > key) { tmp[j+1] = tmp[j]; --j; }
        tmp[j+1] = key;
    }
    for (int i = 0; i < TFULL; ++i) tb->slot[i] = -1;
    for (int k = 0; k < TTRI; ++k) tb->slot[tmp[k]] = k;
}

extern "C" void kernel_launch(void* const* d_in, const int* in_sizes, int n_in,
                              void* d_out, int out_size)
{
    const float* d_offset = (const float*)d_in[0];
    const float* d_topo   = (const float*)d_in[1];
    float* out = (float*)d_out;

    Tables tb;
    if (!tables_from_python(&tb)) {
        fprintf(stderr, "ATHENA: PYFAIL (python table gen unavailable), using fallback RNG\n");
        build_tables_fallback(&tb);
    }

    k_init<<<1, 1>>>();
    k_field<<<NCELL / 128, 128>>>(d_offset, d_topo, tb);
    k_pair<<<NCELL / 256, 256>>>();
    k_fin<<<1, 1>>>(out);
}

// round 4
// speedup vs baseline: 2.5094x; 2.5094x over previous
#include <cuda_runtime.h>
#include <cstdint>
#include <cstring>
#include <cstdio>
#include <cstdlib>

#define WC 48
#define NCELL (48*48*48)
#define TFULL 96
#define TTRI 48
#define OS_A 117649
#define OS_X 2401
#define OS_Y 49
#define BT 64                      // cells (threads) per block in k_field

// Per-triangle recipe: normal n = (c1 + d1*h1 - d0*h0) x (c2 + d2*h2 - d0*h0)
struct TriR {
    float c1x, c1y, c1z, c2x, c2y, c2z;
    float h0x, h0y, h0z, h1x, h1y, h1z, h2x, h2y, h2z;
    int   e0, e1, e2, col, pad;
};
struct Params { TriR r[TTRI]; };   // 48 * 80 B = 3840 B kernel param

__device__ float4 g_sm[NCELL];

// ---------------------------------------------------------------------------
// k_field: one thread per cell; raw topology staging (no gather), recipe math.
// ---------------------------------------------------------------------------
__global__ __launch_bounds__(BT) void k_field(
    const float* __restrict__ off, const float* __restrict__ topo, Params P)
{
    __shared__ float st[BT][97];   // raw 96 topology cols (+pad, odd stride)
    __shared__ float sd[BT][13];   // 12 edge displacements (+pad)

    const int tid   = threadIdx.x;
    const int cell0 = blockIdx.x * BT;

    // stage full topology rows, coalesced float4
    const float4* t4 = reinterpret_cast<const float4*>(topo) + (size_t)cell0 * 24;
    #pragma unroll
    for (int it = 0; it < 24; ++it) {
        int i = tid + it * BT;          // [0, BT*24)
        float4 v = t4[i];
        int r = i / 24, c0 = (i % 24) * 4;
        st[r][c0] = v.x; st[r][c0+1] = v.y; st[r][c0+2] = v.z; st[r][c0+3] = v.w;
    }

    // 12 edge displacements for this cell
    const int c = cell0 + tid;
    const int z = c % WC, y = (c / WC) % WC, x = c / (WC * WC);
    const float* ob = off + x * OS_X + y * OS_Y + z;
    sd[tid][0]  = ob[0];
    sd[tid][1]  = ob[OS_Y];
    sd[tid][2]  = ob[1];
    sd[tid][3]  = ob[OS_Y + 1];
    sd[tid][4]  = ob[OS_A];
    sd[tid][5]  = ob[OS_A + OS_X];
    sd[tid][6]  = ob[OS_A + 1];
    sd[tid][7]  = ob[OS_A + OS_X + 1];
    sd[tid][8]  = ob[2*OS_A];
    sd[tid][9]  = ob[2*OS_A + OS_X];
    sd[tid][10] = ob[2*OS_A + OS_Y];
    sd[tid][11] = ob[2*OS_A + OS_X + OS_Y];

    __syncthreads();

    float s_ = 0.f, mx = 0.f, my = 0.f, mz = 0.f;
    const float* drow = sd[tid];
    const float* trow = st[tid];
    #pragma unroll 4
    for (int t = 0; t < TTRI; ++t) {
        const TriR& R = P.r[t];                 // uniform -> constant broadcast
        float d0 = drow[R.e0], d1 = drow[R.e1], d2 = drow[R.e2];
        float nd0 = -d0;
        float ax = fmaf(d1, R.h1x, fmaf(nd0, R.h0x, R.c1x));
        float ay = fmaf(d1, R.h1y, fmaf(nd0, R.h0y, R.c1y));
        float az = fmaf(d1, R.h1z, fmaf(nd0, R.h0z, R.c1z));
        float bx = fmaf(d2, R.h2x, fmaf(nd0, R.h0x, R.c2x));
        float by = fmaf(d2, R.h2y, fmaf(nd0, R.h0y, R.c2y));
        float bz = fmaf(d2, R.h2z, fmaf(nd0, R.h0z, R.c2z));
        float nx = fmaf(ay, bz, -az * by);
        float ny = fmaf(az, bx, -ax * bz);
        float nz = fmaf(ax, by, -ay * bx);
        float inv = rsqrtf(fmaf(nx, nx, fmaf(ny, ny, fmaf(nz, nz, 1e-8f))));
        float p = trow[R.col];
        s_ += p;
        float w = p * inv;
        mx = fmaf(w, nx, mx); my = fmaf(w, ny, my); mz = fmaf(w, nz, mz);
    }
    g_sm[c] = make_float4(s_, mx, my, mz);
}

// ---------------------------------------------------------------------------
// k_pair: self + forward-neighbor terms; float atomic into out[0]
// ---------------------------------------------------------------------------
__global__ __launch_bounds__(256) void k_pair(float* __restrict__ out)
{
    int c = blockIdx.x * 256 + threadIdx.x;
    int z = c % WC, xy = c / WC, y = xy % WC, x = xy / WC;
    float4 a = g_sm[c];
    float acc = a.x*a.x - a.y*a.y - a.z*a.z - a.w*a.w;
    if (x < WC-1) { float4 b = g_sm[c + WC*WC]; acc += a.x*b.x - a.y*b.y - a.z*b.z - a.w*b.w; }
    if (y < WC-1) { float4 b = g_sm[c + WC];    acc += a.x*b.x - a.y*b.y - a.z*b.z - a.w*b.w; }
    if (z < WC-1) { float4 b = g_sm[c + 1];     acc += a.x*b.x - a.y*b.y - a.z*b.z - a.w*b.w; }
    acc *= 2.0f;
    #pragma unroll
    for (int o = 16; o > 0; o >>= 1) acc += __shfl_down_sync(0xffffffffu, acc, o);
    __shared__ float red[8];
    if ((threadIdx.x & 31) == 0) red[threadIdx.x >> 5] = acc;
    __syncthreads();
    if (threadIdx.x < 8) {
        float v = red[threadIdx.x];
        #pragma unroll
        for (int o = 4; o > 0; o >>= 1) v += __shfl_down_sync(0xffu, v, o);
        if (threadIdx.x == 0) atomicAdd(out, v);
    }
}

// ---------------------------------------------------------------------------
// HOST: edge geometry tables + recipe construction
// ---------------------------------------------------------------------------
static const int EC[12][3] = {{0,0,0},{0,1,0},{0,0,1},{0,1,1},
                              {0,0,0},{1,0,0},{0,0,1},{1,0,1},
                              {0,0,0},{1,0,0},{0,1,0},{1,1,0}};
static const int EA[12] = {0,0,0,0,1,1,1,1,2,2,2,2};

static void make_recipes(const int tri[TTRI][3], const int cols[TTRI], Params* P)
{
    for (int t = 0; t < TTRI; ++t) {
        int e0 = tri[t][0], e1 = tri[t][1], e2 = tri[t][2];
        float b0[3], b1[3], b2[3];
        for (int k = 0; k < 3; ++k) {
            b0[k] = EC[e0][k] + (k == EA[e0] ? 0.5f : 0.f);
            b1[k] = EC[e1][k] + (k == EA[e1] ? 0.5f : 0.f);
            b2[k] = EC[e2][k] + (k == EA[e2] ? 0.5f : 0.f);
        }
        TriR& R = P->r[t];
        R.c1x = b1[0]-b0[0]; R.c1y = b1[1]-b0[1]; R.c1z = b1[2]-b0[2];
        R.c2x = b2[0]-b0[0]; R.c2y = b2[1]-b0[1]; R.c2z = b2[2]-b0[2];
        R.h0x = (EA[e0]==0); R.h0y = (EA[e0]==1); R.h0z = (EA[e0]==2);
        R.h1x = (EA[e1]==0); R.h1y = (EA[e1]==1); R.h1z = (EA[e1]==2);
        R.h2x = (EA[e2]==0); R.h2y = (EA[e2]==1); R.h2z = (EA[e2]==2);
        R.e0 = e0; R.e1 = e1; R.e2 = e2; R.col = cols[t]; R.pad = 0;
    }
}

// ---- ground-truth tables from in-container python/numpy (verified working) ----
static const char* PY_CMD =
    "python3 -c 'import numpy as np;r=np.random.default_rng(0);"
    "a=[r.choice(12,size=3,replace=False) for _ in range(48)];"
    "b=np.sort(r.choice(96,size=48,replace=False));"
    "print(\"TRI=\"+\",\".join(str(int(v)) for t in a for v in t));"
    "print(\"TT=\"+\",\".join(str(int(v)) for v in b))' 2>/dev/null";

static bool tables_from_python(int tri[TTRI][3], int cols[TTRI])
{
    FILE* f = popen(PY_CMD, "r");
    if (!f) return false;
    char l1[1200], l2[1200];
    bool ok = fgets(l1, sizeof l1, f) && fgets(l2, sizeof l2, f) &&
              !strncmp(l1, "TRI=", 4) && !strncmp(l2, "TT=", 3);
    pclose(f);
    if (!ok) return false;
    const char* p = l1 + 4;
    for (int t = 0; t < TTRI; ++t)
        for (int k = 0; k < 3; ++k) {
            char* end; long e = strtol(p, &end, 10);
            if (end == p || e < 0 || e > 11) return false;
            tri[t][k] = (int)e; p = end; if (*p == ',') ++p;
        }
    p = l2 + 3;
    long prev = -1;
    for (int k = 0; k < TTRI; ++k) {
        char* end; long v = strtol(p, &end, 10);
        if (end == p || v <= prev || v >= TFULL) return false;
        cols[k] = (int)v; prev = v; p = end; if (*p == ',') ++p;
    }
    return true;
}

// ---- fallback RNG (SeedSequence(0)+PCG64, Lemire draws everywhere) ----
static void tables_fallback(int tri[TTRI][3], int cols[TTRI])
{
    uint32_t hc = 0x43b0d7e5u;
    auto hashmix = [&hc](uint32_t v) { v ^= hc; hc *= 0x931e8875u; v *= hc; v ^= v >> 16; return v; };
    auto mixf = [](uint32_t a, uint32_t b) { uint32_t r = a*0xca01f9ddu - b*0x4973f715u; return r ^ (r >> 16); };
    uint32_t pool[4];
    for (int i = 0; i < 4; ++i) pool[i] = hashmix(0u);
    for (int s = 0; s < 4; ++s) for (int d2 = 0; d2 < 4; ++d2)
        if (s != d2) pool[d2] = mixf(pool[d2], hashmix(pool[s]));
    uint32_t hb = 0x8b51f9ddu, w[8];
    for (int i = 0; i < 8; ++i) {
        uint32_t v = pool[i % 4]; v ^= hb; hb *= 0x58f38dedu; v *= hb; v ^= v >> 16; w[i] = v;
    }
    uint64_t u64[4];
    for (int k = 0; k < 4; ++k) u64[k] = (uint64_t)w[2*k] | ((uint64_t)w[2*k+1] << 32);
    const __uint128_t MULT = ((__uint128_t)0x2360ed051fc65da4ULL << 64) | 0x4385df649fccf645ULL;
    __uint128_t inc = ((((__uint128_t)u64[2] << 64) | u64[3]) << 1) | 1;
    __uint128_t state = 0;
    state = state * MULT + inc;
    state += ((__uint128_t)u64[0] << 64) | u64[1];
    state = state * MULT + inc;
    bool has32 = false; uint32_t buf32 = 0;
    auto next32 = [&]() -> uint32_t {
        if (has32) { has32 = false; return buf32; }
        state = state * MULT + inc;
        uint64_t hi = (uint64_t)(state >> 64), lo = (uint64_t)state;
        unsigned rot = (unsigned)(hi >> 58);
        uint64_t v = hi ^ lo;
        uint64_t n = (v >> rot) | (v << ((64u - rot) & 63u));
        has32 = true; buf32 = (uint32_t)(n >> 32);
        return (uint32_t)n;
    };
    auto lemire = [&](uint32_t rng) -> uint32_t {
        if (rng == 0) return 0;
        uint32_t re = rng + 1u;
        uint64_t m = (uint64_t)next32() * re;
        uint32_t left = (uint32_t)m;
        if (left < re) {
            uint32_t thr = (0xFFFFFFFFu - rng) % re;
            while (left < thr) { m = (uint64_t)next32() * re; left = (uint32_t)m; }
        }
        return (uint32_t)(m >> 32);
    };
    auto choice = [&](int pop, int size, int64_t* out) {
        uint64_t ss = (uint64_t)(1.2 * (double)size), mask = ss;
        mask|=mask>>1; mask|=mask>>2; mask|=mask>>4; mask|=mask>>8; mask|=mask>>16; mask|=mask>>32;
        int set_size = (int)(mask + 1);
        uint64_t hs[128];
        for (int i = 0; i < set_size; ++i) hs[i] = ~0ULL;
        int k = 0;
        for (int j = pop - size; j < pop; ++j, ++k) {
            uint64_t val = lemire((uint32_t)j);
            uint64_t loc = val & mask;
            while (hs[loc] != ~0ULL && hs[loc] != val) loc = (loc + 1) & mask;
            if (hs[loc] == ~0ULL) { hs[loc] = val; out[k] = (int64_t)val; }
            else {
                loc = (uint64_t)j & mask;
                while (hs[loc] != ~0ULL) loc = (loc + 1) & mask;
                hs[loc] = (uint64_t)j; out[k] = j;
            }
        }
        for (int i = size - 1; i >= 1; --i) {
            uint32_t j = lemire((uint32_t)i);
            int64_t t = out[i]; out[i] = out[j]; out[j] = t;
        }
    };
    int64_t tmp[TTRI];
    for (int t = 0; t < TTRI; ++t) {
        choice(12, 3, tmp);
        tri[t][0] = (int)tmp[0]; tri[t][1] = (int)tmp[1]; tri[t][2] = (int)tmp[2];
    }
    choice(TFULL, TTRI, tmp);
    for (int i = 1; i < TTRI; ++i) {
        int64_t key = tmp[i]; int j = i - 1;
        while (j >= 0 && tmp[j] > key) { tmp[j+1] = tmp[j]; --j; }
        tmp[j+1] = key;
    }
    for (int k = 0; k < TTRI; ++k) cols[k] = (int)tmp[k];
}

// ---------------------------------------------------------------------------
extern "C" void kernel_launch(void* const* d_in, const int* in_sizes, int n_in,
                              void* d_out, int out_size)
{
    const float* d_offset = (const float*)d_in[0];
    const float* d_topo   = (const float*)d_in[1];
    float* out = (float*)d_out;

    int tri[TTRI][3], cols[TTRI];
    if (!tables_from_python(tri, cols)) {
        fprintf(stderr, "ATHENA: PYFAIL, using fallback RNG tables\n");
        tables_fallback(tri, cols);
    }
    Params P;
    make_recipes(tri, cols, &P);

    cudaMemsetAsync(d_out, 0, sizeof(float));
    k_field<<<NCELL / BT, BT>>>(d_offset, d_topo, P);
    k_pair<<<NCELL / 256, 256>>>(out);
}

// round 5
// speedup vs baseline: 3.0707x; 1.2237x over previous
#include <cuda_runtime.h>
#include <cstdint>
#include <cstring>
#include <cstdio>
#include <cstdlib>

#define WC 48
#define NCELL (48*48*48)
#define TFULL 96
#define TTRI 48
#define OS_A 117649
#define OS_X 2401
#define OS_Y 49
#define BT 64                      // cells (threads) per block in k_field

// Per-triangle recipe: n = (c1 + d1*h1 + d0*g0) x (c2 + d2*h2 + d0*g0), g0 = -h0
struct TriR {
    float c1x, c1y, c1z, c2x, c2y, c2z;
    float g0x, g0y, g0z, h1x, h1y, h1z, h2x, h2y, h2z;
    uint32_t epk;                  // e0 | e1<<8 | e2<<16
};
struct Params {
    TriR r[TTRI];                  // 48 * 64 B
    uint32_t slotpack[24];         // col-group g: byte k = slot of col 4g+k (0xFF unused)
};

__device__ float4 g_sm[NCELL];

// ---------------------------------------------------------------------------
// k_field: one thread per cell; compact 48-col staging via shared slot map.
// ---------------------------------------------------------------------------
__global__ __launch_bounds__(BT) void k_field(
    const float* __restrict__ off, const float* __restrict__ topo,
    float* __restrict__ out, Params P)
{
    __shared__ float    st[BT][49];   // 48 gathered topology cols (+pad)
    __shared__ float    sd[BT][13];   // 12 edge displacements (+pad)
    __shared__ uint32_t ssl[24];      // slot map (shared: no divergent LDC)

    const int tid   = threadIdx.x;
    const int cell0 = blockIdx.x * BT;

    if (tid < 24) ssl[tid] = P.slotpack[tid];
    if (cell0 == 0 && tid == 0) out[0] = 0.0f;   // zero accumulator (pre-k_pair)

    // 12 edge displacements for this cell
    const int c = cell0 + tid;
    const int z = c % WC, y = (c / WC) % WC, x = c / (WC * WC);
    const float* ob = off + x * OS_X + y * OS_Y + z;
    sd[tid][0]  = ob[0];
    sd[tid][1]  = ob[OS_Y];
    sd[tid][2]  = ob[1];
    sd[tid][3]  = ob[OS_Y + 1];
    sd[tid][4]  = ob[OS_A];
    sd[tid][5]  = ob[OS_A + OS_X];
    sd[tid][6]  = ob[OS_A + 1];
    sd[tid][7]  = ob[OS_A + OS_X + 1];
    sd[tid][8]  = ob[2*OS_A];
    sd[tid][9]  = ob[2*OS_A + OS_X];
    sd[tid][10] = ob[2*OS_A + OS_Y];
    sd[tid][11] = ob[2*OS_A + OS_X + OS_Y];

    __syncthreads();   // ssl visible

    // stage topology: coalesced float4 loads, scatter needed lanes to slots
    const float4* t4 = reinterpret_cast<const float4*>(topo) + (size_t)cell0 * 24;
    #pragma unroll
    for (int it = 0; it < 24; ++it) {
        int i = tid + it * BT;           // [0, BT*24)
        float4 v = t4[i];
        int r = i / 24, g = i % 24;
        uint32_t sp = ssl[g];
        uint32_t s0 = sp & 0xffu, s1 = (sp >> 8) & 0xffu,
                 s2 = (sp >> 16) & 0xffu, s3 = sp >> 24;
        if (s0 != 0xffu) st[r][s0] = v.x;
        if (s1 != 0xffu) st[r][s1] = v.y;
        if (s2 != 0xffu) st[r][s2] = v.z;
        if (s3 != 0xffu) st[r][s3] = v.w;
    }

    __syncthreads();

    float s_ = 0.f, mx = 0.f, my = 0.f, mz = 0.f;
    const float* drow = sd[tid];
    const float* trow = st[tid];
    #pragma unroll 4
    for (int t = 0; t < TTRI; ++t) {
        const TriR& R = P.r[t];                 // uniform -> constant broadcast
        uint32_t e = R.epk;
        float d0 = drow[e & 0xffu];
        float d1 = drow[(e >> 8) & 0xffu];
        float d2 = drow[(e >> 16) & 0xffu];
        float ax = fmaf(d1, R.h1x, fmaf(d0, R.g0x, R.c1x));
        float ay = fmaf(d1, R.h1y, fmaf(d0, R.g0y, R.c1y));
        float az = fmaf(d1, R.h1z, fmaf(d0, R.g0z, R.c1z));
        float bx = fmaf(d2, R.h2x, fmaf(d0, R.g0x, R.c2x));
        float by = fmaf(d2, R.h2y, fmaf(d0, R.g0y, R.c2y));
        float bz = fmaf(d2, R.h2z, fmaf(d0, R.g0z, R.c2z));
        float nx = fmaf(ay, bz, -az * by);
        float ny = fmaf(az, bx, -ax * bz);
        float nz = fmaf(ax, by, -ay * bx);
        float inv = rsqrtf(fmaf(nx, nx, fmaf(ny, ny, fmaf(nz, nz, 1e-8f))));
        float p = trow[t];                      // slot t == triangle t (sorted map)
        s_ += p;
        float w = p * inv;
        mx = fmaf(w, nx, mx); my = fmaf(w, ny, my); mz = fmaf(w, nz, mz);
    }
    g_sm[c] = make_float4(s_, mx, my, mz);
}

// ---------------------------------------------------------------------------
// k_pair: self + forward-neighbor terms; float atomic into out[0]
// ---------------------------------------------------------------------------
__global__ __launch_bounds__(256) void k_pair(float* __restrict__ out)
{
    int c = blockIdx.x * 256 + threadIdx.x;
    int z = c % WC, xy = c / WC, y = xy % WC, x = xy / WC;
    float4 a = g_sm[c];
    float acc = a.x*a.x - a.y*a.y - a.z*a.z - a.w*a.w;
    if (x < WC-1) { float4 b = g_sm[c + WC*WC]; acc += a.x*b.x - a.y*b.y - a.z*b.z - a.w*b.w; }
    if (y < WC-1) { float4 b = g_sm[c + WC];    acc += a.x*b.x - a.y*b.y - a.z*b.z - a.w*b.w; }
    if (z < WC-1) { float4 b = g_sm[c + 1];     acc += a.x*b.x - a.y*b.y - a.z*b.z - a.w*b.w; }
    acc *= 2.0f;
    #pragma unroll
    for (int o = 16; o > 0; o >>= 1) acc += __shfl_down_sync(0xffffffffu, acc, o);
    __shared__ float red[8];
    if ((threadIdx.x & 31) == 0) red[threadIdx.x >> 5] = acc;
    __syncthreads();
    if (threadIdx.x < 8) {
        float v = red[threadIdx.x];
        #pragma unroll
        for (int o = 4; o > 0; o >>= 1) v += __shfl_down_sync(0xffu, v, o);
        if (threadIdx.x == 0) atomicAdd(out, v);
    }
}

// ---------------------------------------------------------------------------
// HOST: geometry + recipe construction
// ---------------------------------------------------------------------------
static const int EC[12][3] = {{0,0,0},{0,1,0},{0,0,1},{0,1,1},
                              {0,0,0},{1,0,0},{0,0,1},{1,0,1},
                              {0,0,0},{1,0,0},{0,1,0},{1,1,0}};
static const int EA[12] = {0,0,0,0,1,1,1,1,2,2,2,2};

static void make_params(const int tri[TTRI][3], const int cols[TTRI], Params* P)
{
    for (int t = 0; t < TTRI; ++t) {
        int e0 = tri[t][0], e1 = tri[t][1], e2 = tri[t][2];
        float b0[3], b1[3], b2[3];
        for (int k = 0; k < 3; ++k) {
            b0[k] = EC[e0][k] + (k == EA[e0] ? 0.5f : 0.f);
            b1[k] = EC[e1][k] + (k == EA[e1] ? 0.5f : 0.f);
            b2[k] = EC[e2][k] + (k == EA[e2] ? 0.5f : 0.f);
        }
        TriR& R = P->r[t];
        R.c1x = b1[0]-b0[0]; R.c1y = b1[1]-b0[1]; R.c1z = b1[2]-b0[2];
        R.c2x = b2[0]-b0[0]; R.c2y = b2[1]-b0[1]; R.c2z = b2[2]-b0[2];
        R.g0x = -(EA[e0]==0); R.g0y = -(EA[e0]==1); R.g0z = -(EA[e0]==2);
        R.h1x = (EA[e1]==0);  R.h1y = (EA[e1]==1);  R.h1z = (EA[e1]==2);
        R.h2x = (EA[e2]==0);  R.h2y = (EA[e2]==1);  R.h2z = (EA[e2]==2);
        R.epk = (uint32_t)e0 | ((uint32_t)e1 << 8) | ((uint32_t)e2 << 16);
    }
    for (int g = 0; g < 24; ++g) {
        uint32_t sp = 0;
        for (int k = 0; k < 4; ++k) {
            int col = 4*g + k, slot = 0xFF;
            for (int s = 0; s < TTRI; ++s) if (cols[s] == col) { slot = s; break; }
            sp |= (uint32_t)slot << (8*k);
        }
        P->slotpack[g] = sp;
    }
}

// ---- ground-truth tables from in-container python/numpy (verified working) ----
static const char* PY_CMD =
    "python3 -c 'import numpy as np;r=np.random.default_rng(0);"
    "a=[r.choice(12,size=3,replace=False) for _ in range(48)];"
    "b=np.sort(r.choice(96,size=48,replace=False));"
    "print(\"TRI=\"+\",\".join(str(int(v)) for t in a for v in t));"
    "print(\"TT=\"+\",\".join(str(int(v)) for v in b))' 2>/dev/null";

static bool tables_from_python(int tri[TTRI][3], int cols[TTRI])
{
    FILE* f = popen(PY_CMD, "r");
    if (!f) return false;
    char l1[1200], l2[1200];
    bool ok = fgets(l1, sizeof l1, f) && fgets(l2, sizeof l2, f) &&
              !strncmp(l1, "TRI=", 4) && !strncmp(l2, "TT=", 3);
    pclose(f);
    if (!ok) return false;
    const char* p = l1 + 4;
    for (int t = 0; t < TTRI; ++t)
        for (int k = 0; k < 3; ++k) {
            char* end; long e = strtol(p, &end, 10);
            if (end == p || e < 0 || e > 11) return false;
            tri[t][k] = (int)e; p = end; if (*p == ',') ++p;
        }
    p = l2 + 3;
    long prev = -1;
    for (int k = 0; k < TTRI; ++k) {
        char* end; long v = strtol(p, &end, 10);
        if (end == p || v <= prev || v >= TFULL) return false;
        cols[k] = (int)v; prev = v; p = end; if (*p == ',') ++p;
    }
    return true;
}

// ---- fallback RNG (SeedSequence(0)+PCG64, Lemire draws everywhere) ----
static void tables_fallback(int tri[TTRI][3], int cols[TTRI])
{
    uint32_t hc = 0x43b0d7e5u;
    auto hashmix = [&hc](uint32_t v) { v ^= hc; hc *= 0x931e8875u; v *= hc; v ^= v >> 16; return v; };
    auto mixf = [](uint32_t a, uint32_t b) { uint32_t r = a*0xca01f9ddu - b*0x4973f715u; return r ^ (r >> 16); };
    uint32_t pool[4];
    for (int i = 0; i < 4; ++i) pool[i] = hashmix(0u);
    for (int s = 0; s < 4; ++s) for (int d2 = 0; d2 < 4; ++d2)
        if (s != d2) pool[d2] = mixf(pool[d2], hashmix(pool[s]));
    uint32_t hb = 0x8b51f9ddu, w[8];
    for (int i = 0; i < 8; ++i) {
        uint32_t v = pool[i % 4]; v ^= hb; hb *= 0x58f38dedu; v *= hb; v ^= v >> 16; w[i] = v;
    }
    uint64_t u64[4];
    for (int k = 0; k < 4; ++k) u64[k] = (uint64_t)w[2*k] | ((uint64_t)w[2*k+1] << 32);
    const __uint128_t MULT = ((__uint128_t)0x2360ed051fc65da4ULL << 64) | 0x4385df649fccf645ULL;
    __uint128_t inc = ((((__uint128_t)u64[2] << 64) | u64[3]) << 1) | 1;
    __uint128_t state = 0;
    state = state * MULT + inc;
    state += ((__uint128_t)u64[0] << 64) | u64[1];
    state = state * MULT + inc;
    bool has32 = false; uint32_t buf32 = 0;
    auto next32 = [&]() -> uint32_t {
        if (has32) { has32 = false; return buf32; }
        state = state * MULT + inc;
        uint64_t hi = (uint64_t)(state >> 64), lo = (uint64_t)state;
        unsigned rot = (unsigned)(hi >> 58);
        uint64_t v = hi ^ lo;
        uint64_t n = (v >> rot) | (v << ((64u - rot) & 63u));
        has32 = true; buf32 = (uint32_t)(n >> 32);
        return (uint32_t)n;
    };
    auto lemire = [&](uint32_t rng) -> uint32_t {
        if (rng == 0) return 0;
        uint32_t re = rng + 1u;
        uint64_t m = (uint64_t)next32() * re;
        uint32_t left = (uint32_t)m;
        if (left < re) {
            uint32_t thr = (0xFFFFFFFFu - rng) % re;
            while (left < thr) { m = (uint64_t)next32() * re; left = (uint32_t)m; }
        }
        return (uint32_t)(m >> 32);
    };
    auto choice = [&](int pop, int size, int64_t* out) {
        uint64_t ss = (uint64_t)(1.2 * (double)size), mask = ss;
        mask|=mask>>1; mask|=mask>>2; mask|=mask>>4; mask|=mask>>8; mask|=mask>>16; mask|=mask>>32;
        int set_size = (int)(mask + 1);
        uint64_t hs[128];
        for (int i = 0; i < set_size; ++i) hs[i] = ~0ULL;
        int k = 0;
        for (int j = pop - size; j < pop; ++j, ++k) {
            uint64_t val = lemire((uint32_t)j);
            uint64_t loc = val & mask;
            while (hs[loc] != ~0ULL && hs[loc] != val) loc = (loc + 1) & mask;
            if (hs[loc] == ~0ULL) { hs[loc] = val; out[k] = (int64_t)val; }
            else {
                loc = (uint64_t)j & mask;
                while (hs[loc] != ~0ULL) loc = (loc + 1) & mask;
                hs[loc] = (uint64_t)j; out[k] = j;
            }
        }
        for (int i = size - 1; i >= 1; --i) {
            uint32_t j = lemire((uint32_t)i);
            int64_t t = out[i]; out[i] = out[j]; out[j] = t;
        }
    };
    int64_t tmp[TTRI];
    for (int t = 0; t < TTRI; ++t) {
        choice(12, 3, tmp);
        tri[t][0] = (int)tmp[0]; tri[t][1] = (int)tmp[1]; tri[t][2] = (int)tmp[2];
    }
    choice(TFULL, TTRI, tmp);
    for (int i = 1; i < TTRI; ++i) {
        int64_t key = tmp[i]; int j = i - 1;
        while (j >= 0 && tmp[j] > key) { tmp[j+1] = tmp[j]; --j; }
        tmp[j+1] = key;
    }
    for (int k = 0; k < TTRI; ++k) cols[k] = (int)tmp[k];
}

// ---------------------------------------------------------------------------
extern "C" void kernel_launch(void* const* d_in, const int* in_sizes, int n_in,
                              void* d_out, int out_size)
{
    const float* d_offset = (const float*)d_in[0];
    const float* d_topo   = (const float*)d_in[1];
    float* out = (float*)d_out;

    int tri[TTRI][3], cols[TTRI];
    if (!tables_from_python(tri, cols)) {
        fprintf(stderr, "ATHENA: PYFAIL, using fallback RNG tables\n");
        tables_fallback(tri, cols);
    }
    Params P;
    make_params(tri, cols, &P);

    k_field<<<NCELL / BT, BT>>>(d_offset, d_topo, out, P);
    k_pair<<<NCELL / 256, 256>>>(out);
}